// round 4
// baseline (speedup 1.0000x reference)
#include <cuda_runtime.h>
#include <stdint.h>

// MyDropout: out = x * mask; mask = JAX threefry dropout (seed 42, p=0.1),
// columns < 64 forced to zero. x: [16384, 4096] f32, N = 67108864.
//
// JAX >= 0.4.36 default: jax_threefry_partitionable = True, so
//   bits(i) = o0 ^ o1  where (o0, o1) = threefry2x32(key=(0,42), ctr=(0, i))
// keep  <=>  (bits >> 9) < 0x733333   (== uniform < 0.9f, exact)

#define TF_ROT(x, r) (((x) << (r)) | ((x) >> (32 - (r))))
#define TF_ROUND(r) do { x0 += x1; x1 = TF_ROT(x1, r); x1 ^= x0; } while (0)

__device__ __forceinline__ uint32_t tf_bits(uint32_t i) {
    const uint32_t k0 = 0u;
    const uint32_t k1 = 42u;
    const uint32_t k2 = 0x1BD11BDAu ^ k0 ^ k1;  // 0x1BD11BF0

    uint32_t x0 = k0;        // counts_hi = 0, + k0
    uint32_t x1 = i + k1;    // counts_lo = i, + k1
    TF_ROUND(13); TF_ROUND(15); TF_ROUND(26); TF_ROUND(6);
    x0 += k1; x1 += k2 + 1u;
    TF_ROUND(17); TF_ROUND(29); TF_ROUND(16); TF_ROUND(24);
    x0 += k2; x1 += k0 + 2u;
    TF_ROUND(13); TF_ROUND(15); TF_ROUND(26); TF_ROUND(6);
    x0 += k0; x1 += k1 + 3u;
    TF_ROUND(17); TF_ROUND(29); TF_ROUND(16); TF_ROUND(24);
    x0 += k1; x1 += k2 + 4u;
    TF_ROUND(13); TF_ROUND(15); TF_ROUND(26); TF_ROUND(6);
    x0 += k2; x1 += k0 + 5u;
    return x0 ^ x1;          // partitionable 32-bit output
}

__global__ __launch_bounds__(256) void mydropout_kernel(
    const float4* __restrict__ x, float4* __restrict__ out) {
    const uint32_t KEEP_THRESH = 0x733333u;   // (bits>>9) < this  <=>  u < 0.9f
    const float scale = (float)(1.0 / 0.9);

    uint32_t tid = blockIdx.x * blockDim.x + threadIdx.x;  // one float4 / thread
    uint32_t g = tid << 2;                                 // element index
    uint32_t col = g & 4095u;                              // column (row width 4096)

    if (col < 64u) {
        // K=64 leading columns are zeroed; float4-aligned, so whole vector is zero.
        out[tid] = make_float4(0.f, 0.f, 0.f, 0.f);
        return;
    }

    float4 a = x[tid];

    uint32_t b0 = tf_bits(g + 0u);
    uint32_t b1 = tf_bits(g + 1u);
    uint32_t b2 = tf_bits(g + 2u);
    uint32_t b3 = tf_bits(g + 3u);

    float4 r;
    r.x = ((b0 >> 9) < KEEP_THRESH) ? a.x * scale : 0.f;
    r.y = ((b1 >> 9) < KEEP_THRESH) ? a.y * scale : 0.f;
    r.z = ((b2 >> 9) < KEEP_THRESH) ? a.z * scale : 0.f;
    r.w = ((b3 >> 9) < KEEP_THRESH) ? a.w * scale : 0.f;

    out[tid] = r;
}

extern "C" void kernel_launch(void* const* d_in, const int* in_sizes, int n_in,
                              void* d_out, int out_size) {
    const float4* x = (const float4*)d_in[0];
    float4* out = (float4*)d_out;
    const int threads = 256;
    const int blocks = 16777216 / threads;  // N/4 threads = 16,777,216
    mydropout_kernel<<<blocks, threads>>>(x, out);
}